// round 2
// baseline (speedup 1.0000x reference)
#include <cuda_runtime.h>
#include <math.h>

#define Nn 65536
#define Kc 8
#define Hs 128
#define Tt 4

// Scratch (allocation-free rule: __device__ globals)
__device__ int   g_cnt[Tt];
__device__ int   g_perm[Tt][Nn];
__device__ float g_hsum[(size_t)Nn * Hs];

// ---------------------------------------------------------------------------
// Bucket nodes by type (block-aggregated atomics)
// ---------------------------------------------------------------------------
__global__ void k_zero() {
    if (threadIdx.x < Tt) g_cnt[threadIdx.x] = 0;
}

__global__ void __launch_bounds__(256) k_bucket(const int* __restrict__ type_id) {
    __shared__ int scnt[Tt];
    __shared__ int sbase[Tt];
    const int tid = threadIdx.x;
    if (tid < Tt) scnt[tid] = 0;
    __syncthreads();
    const int n = blockIdx.x * 256 + tid;
    const int t = type_id[n];
    const int local = atomicAdd(&scnt[t], 1);
    __syncthreads();
    if (tid < Tt) sbase[tid] = atomicAdd(&g_cnt[tid], scnt[tid]);
    __syncthreads();
    g_perm[t][sbase[t] + local] = n;
}

// ---------------------------------------------------------------------------
// Kernel F: per-type forget-gate GEMVs + sigmoid + c reduction; also h_sum.
// U_f[t] (64KB fp32) resident in smem; nodes streamed via bucket perm.
// Thread j owns output column j; h tile transposed to [i][k] (double-buffered)
// so inner loop is 1x LDS.32 (U, conflict-free) + 2x broadcast LDS.128 per
// 8 FFMA -> FFMA-pipe-bound.
// ---------------------------------------------------------------------------
__global__ void __launch_bounds__(128) k_fgate(
    const float* __restrict__ h, const float* __restrict__ c,
    const float* __restrict__ f_input,
    const float* __restrict__ U_f, const float* __restrict__ b_f,
    float* __restrict__ out)
{
    const int t   = blockIdx.y;
    const int tid = threadIdx.x;
    extern __shared__ float sm[];
    float* Us   = sm;                         // 128*128 fp32 = 64KB
    float* hbuf = sm + Hs * Hs;               // 2 x (128*8) fp32, [i][k]

    // Load U_f[t] into smem (vectorized, coalesced)
    {
        const float4* Ug  = (const float4*)(U_f + (size_t)t * Hs * Hs);
        float4*       Us4 = (float4*)Us;
        #pragma unroll
        for (int x = tid; x < (Hs * Hs) / 4; x += 128) Us4[x] = Ug[x];
    }
    const float bf = b_f[t * Hs + tid];
    __syncthreads();

    const int cnt = g_cnt[t];
    int buf = 0;
    for (int s = blockIdx.x; s < cnt; s += gridDim.x, buf ^= 1) {
        const int n = g_perm[t][s];
        const float* hrow = h + (size_t)n * Kc * Hs;
        float* hsh = hbuf + buf * (Hs * Kc);

        // Load h tile (coalesced), transpose to [i][k], fuse h_sum
        float hs = 0.f;
        #pragma unroll
        for (int k = 0; k < Kc; k++) {
            float v = hrow[k * Hs + tid];
            hs += v;
            hsh[tid * Kc + k] = v;
        }
        g_hsum[(size_t)n * Hs + tid] = hs;
        const float fi = f_input[(size_t)n * Hs + tid];
        __syncthreads();

        float acc[Kc];
        #pragma unroll
        for (int k = 0; k < Kc; k++) acc[k] = 0.f;

        #pragma unroll 4
        for (int i = 0; i < Hs; i++) {
            const float  u = Us[i * Hs + tid];
            const float4 a = *(const float4*)&hsh[i * Kc];
            const float4 b = *(const float4*)&hsh[i * Kc + 4];
            acc[0] += u * a.x; acc[1] += u * a.y; acc[2] += u * a.z; acc[3] += u * a.w;
            acc[4] += u * b.x; acc[5] += u * b.y; acc[6] += u * b.z; acc[7] += u * b.w;
        }

        // Epilogue: sigmoid + weighted c reduction
        float ca = 0.f;
        const float* crow = c + (size_t)n * Kc * Hs;
        #pragma unroll
        for (int k = 0; k < Kc; k++) {
            float x  = fi + acc[k] + bf;
            float fg = 1.f / (1.f + __expf(-x));
            ca += fg * crow[k * Hs + tid];
        }
        out[(size_t)n * 4 * Hs + 3 * Hs + tid] = ca;
        // no trailing sync: next iteration writes the other buffer
    }
}

// ---------------------------------------------------------------------------
// Kernel I: per-type iou GEMV. U_iou[t] (192KB fp32) resident in smem
// (1 block/SM). Register-blocks 8 nodes; h_sum packed [i][node] double-
// buffered; inner loop 1x LDS.32 (U) + 2x broadcast LDS.128 per 8 FFMA.
// ---------------------------------------------------------------------------
__global__ void __launch_bounds__(384) k_iou(
    const float* __restrict__ U_iou, const float* __restrict__ b_iou,
    float* __restrict__ out)
{
    const int t   = blockIdx.y;
    const int tid = threadIdx.x;   // 0..383, column index
    extern __shared__ float sm[];
    float* Us   = sm;                   // 128*384 fp32 = 192KB
    float* hbuf = sm + Hs * 3 * Hs;     // 2 x (128*8), [i][r]

    {
        const float4* Ug  = (const float4*)(U_iou + (size_t)t * Hs * 3 * Hs);
        float4*       Us4 = (float4*)Us;
        for (int x = tid; x < (Hs * 3 * Hs) / 4; x += 384) Us4[x] = Ug[x];
    }
    const float bi = b_iou[t * 3 * Hs + tid];
    __syncthreads();

    const int cnt     = g_cnt[t];
    const int ngroups = (cnt + 7) >> 3;
    int buf = 0;
    for (int g = blockIdx.x; g < ngroups; g += gridDim.x, buf ^= 1) {
        const int base = g * 8;
        const int m    = min(8, cnt - base);
        float* hsh = hbuf + buf * (Hs * 8);

        // Pack up to 8 nodes' h_sum rows into [i][r] (coalesced global reads)
        for (int x = tid; x < Hs * 8; x += 384) {
            const int r = x >> 7;
            const int i = x & (Hs - 1);
            float v = 0.f;
            if (r < m) v = g_hsum[(size_t)g_perm[t][base + r] * Hs + i];
            hsh[i * 8 + r] = v;
        }
        __syncthreads();

        float acc[8];
        #pragma unroll
        for (int r = 0; r < 8; r++) acc[r] = 0.f;

        #pragma unroll 4
        for (int i = 0; i < Hs; i++) {
            const float  u = Us[i * 3 * Hs + tid];
            const float4 a = *(const float4*)&hsh[i * 8];
            const float4 b = *(const float4*)&hsh[i * 8 + 4];
            acc[0] += u * a.x; acc[1] += u * a.y; acc[2] += u * a.z; acc[3] += u * a.w;
            acc[4] += u * b.x; acc[5] += u * b.y; acc[6] += u * b.z; acc[7] += u * b.w;
        }

        for (int r = 0; r < m; r++) {
            const int n = g_perm[t][base + r];
            out[(size_t)n * 4 * Hs + tid] = acc[r] + bi;
        }
        // no trailing sync: next group writes the other buffer
    }
}

// ---------------------------------------------------------------------------
extern "C" void kernel_launch(void* const* d_in, const int* in_sizes, int n_in,
                              void* d_out, int out_size)
{
    const float* h       = (const float*)d_in[0];
    const float* c       = (const float*)d_in[1];
    const float* f_input = (const float*)d_in[2];
    const int*   type_id = (const int*)  d_in[3];
    const float* U_iou   = (const float*)d_in[4];
    const float* b_iou   = (const float*)d_in[5];
    const float* U_f     = (const float*)d_in[6];
    const float* b_f     = (const float*)d_in[7];
    float*       out     = (float*)d_out;

    const int smemF = (Hs * Hs + 2 * Hs * Kc) * (int)sizeof(float);       // ~68KB
    const int smemI = (Hs * 3 * Hs + 2 * Hs * Kc) * (int)sizeof(float);   // ~200KB
    cudaFuncSetAttribute(k_fgate, cudaFuncAttributeMaxDynamicSharedMemorySize, smemF);
    cudaFuncSetAttribute(k_iou,   cudaFuncAttributeMaxDynamicSharedMemorySize, smemI);

    k_zero<<<1, 32>>>();
    k_bucket<<<Nn / 256, 256>>>(type_id);

    dim3 gf(444, Tt);   // 3 resident blocks/SM (~68KB smem) * 148 SMs
    k_fgate<<<gf, 128, smemF>>>(h, c, f_input, U_f, b_f, out);

    dim3 gi(148, Tt);   // 1 resident block/SM (~200KB smem)
    k_iou<<<gi, 384, smemI>>>(U_iou, b_iou, out);
}

// round 5
// speedup vs baseline: 2.0185x; 2.0185x over previous
#include <cuda_runtime.h>
#include <cuda_bf16.h>
#include <cstdint>
#include <math.h>

#define Nn 65536
#define Kc 8
#define Hs 128
#define Tt 4
#define APAD 136          // padded row stride in bf16 elems (272B: conflict-free ldmatrix)

// ---------------------------------------------------------------------------
// Device scratch (allocation-free rule: __device__ globals)
// ---------------------------------------------------------------------------
__device__ int   g_cnt[Tt];
__device__ int   g_perm[Tt][Nn];
__device__ float g_hsum[(size_t)Nn * Hs];
// bf16 hi/lo images of U_f and U_iou (plain row-major [i][j], K=i rows)
__device__ __align__(16) __nv_bfloat16 g_Bf[2][Tt][Hs * Hs];
__device__ __align__(16) __nv_bfloat16 g_Bi[2][Tt][3][Hs * Hs];

// ---------------------------------------------------------------------------
// Warp-MMA helpers (sm_80-class: valid on plain sm_103 target)
// ---------------------------------------------------------------------------
__device__ __forceinline__ uint32_t smem_to_u32(const void* p) {
    uint32_t a;
    asm("{ .reg .u64 t; cvta.to.shared.u64 t, %1; cvt.u32.u64 %0, t; }" : "=r"(a) : "l"(p));
    return a;
}
__device__ __forceinline__ void ldm_x4(uint32_t* r, uint32_t a) {
    asm volatile("ldmatrix.sync.aligned.m8n8.x4.shared.b16 {%0,%1,%2,%3}, [%4];"
        : "=r"(r[0]), "=r"(r[1]), "=r"(r[2]), "=r"(r[3]) : "r"(a));
}
__device__ __forceinline__ void ldm_x4t(uint32_t* r, uint32_t a) {
    asm volatile("ldmatrix.sync.aligned.m8n8.x4.trans.shared.b16 {%0,%1,%2,%3}, [%4];"
        : "=r"(r[0]), "=r"(r[1]), "=r"(r[2]), "=r"(r[3]) : "r"(a));
}
__device__ __forceinline__ void mma16816(float* c, const uint32_t* a, const uint32_t* b) {
    asm volatile("mma.sync.aligned.m16n8k16.row.col.f32.bf16.bf16.f32 "
        "{%0,%1,%2,%3}, {%4,%5,%6,%7}, {%8,%9}, {%0,%1,%2,%3};"
        : "+f"(c[0]), "+f"(c[1]), "+f"(c[2]), "+f"(c[3])
        : "r"(a[0]), "r"(a[1]), "r"(a[2]), "r"(a[3]), "r"(b[0]), "r"(b[1]));
}
__device__ __forceinline__ void bf16_split2(float x, float y,
                                            __nv_bfloat162& hi, __nv_bfloat162& lo) {
    hi = __floats2bfloat162_rn(x, y);
    lo = __floats2bfloat162_rn(x - __bfloat162float(hi.x), y - __bfloat162float(hi.y));
}

// ---------------------------------------------------------------------------
// Bucket nodes by type
// ---------------------------------------------------------------------------
__global__ void k_zero() { if (threadIdx.x < Tt) g_cnt[threadIdx.x] = 0; }

__global__ void __launch_bounds__(256) k_bucket(const int* __restrict__ type_id) {
    __shared__ int scnt[Tt];
    __shared__ int sbase[Tt];
    const int tid = threadIdx.x;
    if (tid < Tt) scnt[tid] = 0;
    __syncthreads();
    const int n = blockIdx.x * 256 + tid;
    const int t = type_id[n];
    const int local = atomicAdd(&scnt[t], 1);
    __syncthreads();
    if (tid < Tt) sbase[tid] = atomicAdd(&g_cnt[tid], scnt[tid]);
    __syncthreads();
    g_perm[t][sbase[t] + local] = n;
}

// ---------------------------------------------------------------------------
// Weight prep: bf16 hi/lo split of U_f and U_iou (row-major [i][j])
// ---------------------------------------------------------------------------
__global__ void __launch_bounds__(256) k_prepw(const float* __restrict__ U_iou,
                                               const float* __restrict__ U_f) {
    int idx = blockIdx.x * 256 + threadIdx.x;     // 4 * 4 * 16384 = 262144
    int t   = idx >> 16;
    int rem = idx & 65535;
    int m   = rem >> 14;                          // 0 = f, 1..3 = iou jtile
    int i   = (rem >> 7) & 127;
    int j   = rem & 127;
    float v = (m == 0) ? U_f[((size_t)t * Hs + i) * Hs + j]
                       : U_iou[((size_t)t * Hs + i) * 3 * Hs + (m - 1) * Hs + j];
    __nv_bfloat16 hi = __float2bfloat16(v);
    __nv_bfloat16 lo = __float2bfloat16(v - __bfloat162float(hi));
    int e = i * Hs + j;
    if (m == 0) { g_Bf[0][t][e] = hi; g_Bf[1][t][e] = lo; }
    else        { g_Bi[0][t][m - 1][e] = hi; g_Bi[1][t][m - 1][e] = lo; }
}

// ---------------------------------------------------------------------------
// k_fmma: 16 nodes/CTA, rows = nl*8+k (M=128), K=128, N=128.
// D = h_tile @ U_f[t] via 3-pass bf16-split mma.sync; fused h_sum + sigmoid*c
// epilogue with smem-staged k-reduction.
// smem: A_hi[128][136] | A_lo | B_hi | B_lo (34816B each) | s_node
// stage (fp32 128x136) aliases A_hi+A_lo after MMA completes.
// ---------------------------------------------------------------------------
__global__ void __launch_bounds__(256) k_fmma(
    const float* __restrict__ h, const float* __restrict__ c_in,
    const float* __restrict__ f_input, const float* __restrict__ b_f,
    float* __restrict__ out)
{
    const int t = blockIdx.y;
    const int cnt = g_cnt[t];
    const int tile = blockIdx.x;
    if (tile * 16 >= cnt) return;

    extern __shared__ __align__(16) char sm[];
    __nv_bfloat16* Ah = (__nv_bfloat16*)sm;
    __nv_bfloat16* Al = Ah + Hs * APAD;
    __nv_bfloat16* Bh = Al + Hs * APAD;
    __nv_bfloat16* Bl = Bh + Hs * APAD;
    float*         stage = (float*)sm;                  // aliases Ah+Al (69632B)
    int*           s_node = (int*)(sm + 4 * Hs * APAD * 2);
    const uint32_t su = smem_to_u32(sm);
    const uint32_t aHi = su, aLo = su + 34816, bHi = su + 69632, bLo = su + 104448;

    const int tid  = threadIdx.x;
    const int wid  = tid >> 5, lane = tid & 31;

    if (tid < 16) s_node[tid] = g_perm[t][min(tile * 16 + tid, cnt - 1)];
    __syncthreads();

    // ---- A gather: split h to bf16 hi/lo, fuse h_sum -> global ----
    {
        const int cp  = (tid & 63) * 2;
        const int grp = tid >> 6;
        #pragma unroll
        for (int nn = 0; nn < 4; nn++) {
            const int nl = grp * 4 + nn;
            const size_t nb = (size_t)s_node[nl] * (Kc * Hs);
            float hx = 0.f, hy = 0.f;
            #pragma unroll
            for (int k = 0; k < Kc; k++) {
                float2 v = *(const float2*)(h + nb + k * Hs + cp);
                hx += v.x; hy += v.y;
                __nv_bfloat162 hi2, lo2;
                bf16_split2(v.x, v.y, hi2, lo2);
                const int row = nl * 8 + k;
                *(__nv_bfloat162*)(Ah + row * APAD + cp) = hi2;
                *(__nv_bfloat162*)(Al + row * APAD + cp) = lo2;
            }
            float2 hs = make_float2(hx, hy);
            *(float2*)(g_hsum + (size_t)s_node[nl] * Hs + cp) = hs;
        }
    }
    // ---- B copy (pre-split, L2-hot), add padding ----
    {
        const uint4* sh = (const uint4*)g_Bf[0][t];
        const uint4* sl = (const uint4*)g_Bf[1][t];
        #pragma unroll
        for (int i = tid; i < 2048; i += 256) {
            int row = i >> 4, q = i & 15;
            *(uint4*)(Bh + row * APAD + q * 8) = sh[i];
            *(uint4*)(Bl + row * APAD + q * 8) = sl[i];
        }
    }
    __syncthreads();

    // ---- 3-pass MMA ----
    const int wm = wid & 3, wn = wid >> 2;
    const int l15 = lane & 15, lh = (lane >> 4) << 3;
    float acc[2][8][4];
    #pragma unroll
    for (int mt = 0; mt < 2; mt++)
        #pragma unroll
        for (int nt = 0; nt < 8; nt++)
            #pragma unroll
            for (int e = 0; e < 4; e++) acc[mt][nt][e] = 0.f;

    #pragma unroll
    for (int pass = 0; pass < 3; pass++) {
        const uint32_t Ab = (pass == 2) ? aLo : aHi;
        const uint32_t Bb = (pass == 1) ? bLo : bHi;
        #pragma unroll
        for (int ks = 0; ks < 8; ks++) {
            uint32_t a[2][4];
            #pragma unroll
            for (int mt = 0; mt < 2; mt++)
                ldm_x4(a[mt], Ab + (((wm * 32 + mt * 16 + l15) * APAD + ks * 16 + lh) << 1));
            uint32_t b[8][2];
            #pragma unroll
            for (int nb = 0; nb < 4; nb++) {
                uint32_t r[4];
                ldm_x4t(r, Bb + (((ks * 16 + l15) * APAD + wn * 64 + nb * 16 + lh) << 1));
                b[nb * 2][0] = r[0]; b[nb * 2][1] = r[1];
                b[nb * 2 + 1][0] = r[2]; b[nb * 2 + 1][1] = r[3];
            }
            #pragma unroll
            for (int mt = 0; mt < 2; mt++)
                #pragma unroll
                for (int nt = 0; nt < 8; nt++)
                    mma16816(acc[mt][nt], a[mt], b[nt]);
        }
    }
    __syncthreads();   // all warps done reading A before stage overwrites it

    // ---- Epilogue: sigmoid(D + f_input + b_f) * c -> stage ----
    {
        const int q  = lane & 3;           // col quad
        const int lr = lane >> 2;          // row-in-8
        float2 bfv[8];
        #pragma unroll
        for (int nt = 0; nt < 8; nt++)
            bfv[nt] = *(const float2*)(b_f + t * Hs + wn * 64 + nt * 8 + q * 2);
        #pragma unroll
        for (int mt = 0; mt < 2; mt++) {
            #pragma unroll
            for (int half = 0; half < 2; half++) {
                const int row = wm * 32 + mt * 16 + lr + half * 8;
                const int nl = row >> 3, kk = row & 7;
                const size_t node = (size_t)s_node[nl];
                const float* fi = f_input + node * Hs;
                const float* cr = c_in + node * (Kc * Hs) + kk * Hs;
                #pragma unroll
                for (int nt = 0; nt < 8; nt++) {
                    const int col = wn * 64 + nt * 8 + q * 2;
                    float2 f2 = *(const float2*)(fi + col);
                    float2 c2 = *(const float2*)(cr + col);
                    float x0 = acc[mt][nt][half * 2 + 0] + f2.x + bfv[nt].x;
                    float x1 = acc[mt][nt][half * 2 + 1] + f2.y + bfv[nt].y;
                    float g0 = 1.f / (1.f + __expf(-x0));
                    float g1 = 1.f / (1.f + __expf(-x1));
                    *(float2*)(stage + row * APAD + col) = make_float2(g0 * c2.x, g1 * c2.y);
                }
            }
        }
    }
    __syncthreads();

    // ---- k-reduction + coalesced c_aggr store ----
    #pragma unroll
    for (int x = tid; x < 16 * Hs; x += 256) {
        const int nl = x >> 7, j = x & 127;
        if (tile * 16 + nl < cnt) {
            float s = 0.f;
            #pragma unroll
            for (int k = 0; k < Kc; k++) s += stage[(nl * 8 + k) * APAD + j];
            out[(size_t)s_node[nl] * (4 * Hs) + 3 * Hs + j] = s;
        }
    }
}

// ---------------------------------------------------------------------------
// k_imma: 128 nodes/CTA (M=128 rows = h_sum), K=128, 3 j-tiles of N=128.
// Direct register epilogue with sector-aligned float2 stores.
// ---------------------------------------------------------------------------
__global__ void __launch_bounds__(256) k_imma(
    const float* __restrict__ b_iou, float* __restrict__ out)
{
    const int t = blockIdx.y;
    const int cnt = g_cnt[t];
    const int tile = blockIdx.x;
    if (tile * 128 >= cnt) return;

    extern __shared__ __align__(16) char sm[];
    __nv_bfloat16* Ah = (__nv_bfloat16*)sm;
    __nv_bfloat16* Al = Ah + Hs * APAD;
    __nv_bfloat16* Bh = Al + Hs * APAD;
    __nv_bfloat16* Bl = Bh + Hs * APAD;
    int*           s_node = (int*)(sm + 4 * Hs * APAD * 2);
    const uint32_t su = smem_to_u32(sm);
    const uint32_t aHi = su, aLo = su + 34816, bHi = su + 69632, bLo = su + 104448;

    const int tid = threadIdx.x;
    const int wid = tid >> 5, lane = tid & 31;

    if (tid < 128) s_node[tid] = g_perm[t][min(tile * 128 + tid, cnt - 1)];
    __syncthreads();

    // ---- A gather: split h_sum rows ----
    {
        const int cp  = (tid & 63) * 2;
        const int grp = tid >> 6;
        #pragma unroll 4
        for (int rr = 0; rr < 32; rr++) {
            const int row = grp * 32 + rr;
            float2 v = *(const float2*)(g_hsum + (size_t)s_node[row] * Hs + cp);
            __nv_bfloat162 hi2, lo2;
            bf16_split2(v.x, v.y, hi2, lo2);
            *(__nv_bfloat162*)(Ah + row * APAD + cp) = hi2;
            *(__nv_bfloat162*)(Al + row * APAD + cp) = lo2;
        }
    }

    const int wm = wid & 3, wn = wid >> 2;
    const int l15 = lane & 15, lh = (lane >> 4) << 3;
    const int q = lane & 3, lr = lane >> 2;

    for (int jt = 0; jt < 3; jt++) {
        __syncthreads();   // prior MMA done before B overwrite (A write covered on jt=0)
        {
            const uint4* sh = (const uint4*)g_Bi[0][t][jt];
            const uint4* sl = (const uint4*)g_Bi[1][t][jt];
            #pragma unroll
            for (int i = tid; i < 2048; i += 256) {
                int row = i >> 4, qq = i & 15;
                *(uint4*)(Bh + row * APAD + qq * 8) = sh[i];
                *(uint4*)(Bl + row * APAD + qq * 8) = sl[i];
            }
        }
        __syncthreads();

        float acc[2][8][4];
        #pragma unroll
        for (int mt = 0; mt < 2; mt++)
            #pragma unroll
            for (int nt = 0; nt < 8; nt++)
                #pragma unroll
                for (int e = 0; e < 4; e++) acc[mt][nt][e] = 0.f;

        #pragma unroll
        for (int pass = 0; pass < 3; pass++) {
            const uint32_t Ab = (pass == 2) ? aLo : aHi;
            const uint32_t Bb = (pass == 1) ? bLo : bHi;
            #pragma unroll
            for (int ks = 0; ks < 8; ks++) {
                uint32_t a[2][4];
                #pragma unroll
                for (int mt = 0; mt < 2; mt++)
                    ldm_x4(a[mt], Ab + (((wm * 32 + mt * 16 + l15) * APAD + ks * 16 + lh) << 1));
                uint32_t b[8][2];
                #pragma unroll
                for (int nb = 0; nb < 4; nb++) {
                    uint32_t r[4];
                    ldm_x4t(r, Bb + (((ks * 16 + l15) * APAD + wn * 64 + nb * 16 + lh) << 1));
                    b[nb * 2][0] = r[0]; b[nb * 2][1] = r[1];
                    b[nb * 2 + 1][0] = r[2]; b[nb * 2 + 1][1] = r[3];
                }
                #pragma unroll
                for (int mt = 0; mt < 2; mt++)
                    #pragma unroll
                    for (int nt = 0; nt < 8; nt++)
                        mma16816(acc[mt][nt], a[mt], b[nt]);
            }
        }

        // ---- Direct epilogue: + b_iou, store ----
        float2 bv[8];
        #pragma unroll
        for (int nt = 0; nt < 8; nt++)
            bv[nt] = *(const float2*)(b_iou + (size_t)t * 3 * Hs + jt * Hs + wn * 64 + nt * 8 + q * 2);
        #pragma unroll
        for (int mt = 0; mt < 2; mt++) {
            #pragma unroll
            for (int half = 0; half < 2; half++) {
                const int row = wm * 32 + mt * 16 + lr + half * 8;
                if (tile * 128 + row < cnt) {
                    float* orow = out + (size_t)s_node[row] * (4 * Hs) + jt * Hs;
                    #pragma unroll
                    for (int nt = 0; nt < 8; nt++) {
                        const int col = wn * 64 + nt * 8 + q * 2;
                        *(float2*)(orow + col) = make_float2(
                            acc[mt][nt][half * 2 + 0] + bv[nt].x,
                            acc[mt][nt][half * 2 + 1] + bv[nt].y);
                    }
                }
            }
        }
    }
}

// ---------------------------------------------------------------------------
extern "C" void kernel_launch(void* const* d_in, const int* in_sizes, int n_in,
                              void* d_out, int out_size)
{
    const float* h       = (const float*)d_in[0];
    const float* c       = (const float*)d_in[1];
    const float* f_input = (const float*)d_in[2];
    const int*   type_id = (const int*)  d_in[3];
    const float* U_iou   = (const float*)d_in[4];
    const float* b_iou   = (const float*)d_in[5];
    const float* U_f     = (const float*)d_in[6];
    const float* b_f     = (const float*)d_in[7];
    float*       out     = (float*)d_out;

    const int smemF = 4 * Hs * APAD * 2 + 16 * 4;    // 139328
    const int smemI = 4 * Hs * APAD * 2 + 128 * 4;   // 139776
    cudaFuncSetAttribute(k_fmma, cudaFuncAttributeMaxDynamicSharedMemorySize, smemF);
    cudaFuncSetAttribute(k_imma, cudaFuncAttributeMaxDynamicSharedMemorySize, smemI);

    k_zero<<<1, 32>>>();
    k_bucket<<<Nn / 256, 256>>>(type_id);
    k_prepw<<<1024, 256>>>(U_iou, U_f);

    dim3 gf(Nn / 16, Tt);
    k_fmma<<<gf, 256, smemF>>>(h, c, f_input, b_f, out);

    dim3 gi(Nn / 128, Tt);
    k_imma<<<gi, 256, smemI>>>(b_iou, out);
}

// round 6
// speedup vs baseline: 2.6015x; 1.2888x over previous
#include <cuda_runtime.h>
#include <cuda_bf16.h>
#include <cstdint>
#include <math.h>

#define Nn 65536
#define Kc 8
#define Hs 128
#define Tt 4
#define APAD 136          // padded row stride in bf16 elems (272B: conflict-free ldmatrix)

// ---------------------------------------------------------------------------
// Device scratch (allocation-free rule: __device__ globals)
// ---------------------------------------------------------------------------
__device__ int   g_cnt[Tt];
__device__ int   g_perm[Tt][Nn];
__device__ int   g_baseF[Tt + 1];   // tile bases, 8 nodes/tile
__device__ int   g_baseI[Tt + 1];   // tile bases, 64 nodes/tile
__device__ float g_hsum[(size_t)Nn * Hs];
// bf16 hi/lo images of U_f and U_iou (plain row-major [i][j], K=i rows)
__device__ __align__(16) __nv_bfloat16 g_Bf[2][Tt][Hs * Hs];
__device__ __align__(16) __nv_bfloat16 g_Bi[2][Tt][3][Hs * Hs];

// ---------------------------------------------------------------------------
// Warp-MMA helpers (sm_80-class: valid on plain sm_103 target)
// ---------------------------------------------------------------------------
__device__ __forceinline__ uint32_t smem_to_u32(const void* p) {
    uint32_t a;
    asm("{ .reg .u64 t; cvta.to.shared.u64 t, %1; cvt.u32.u64 %0, t; }" : "=r"(a) : "l"(p));
    return a;
}
__device__ __forceinline__ void ldm_x4(uint32_t* r, uint32_t a) {
    asm volatile("ldmatrix.sync.aligned.m8n8.x4.shared.b16 {%0,%1,%2,%3}, [%4];"
        : "=r"(r[0]), "=r"(r[1]), "=r"(r[2]), "=r"(r[3]) : "r"(a));
}
__device__ __forceinline__ void ldm_x4t(uint32_t* r, uint32_t a) {
    asm volatile("ldmatrix.sync.aligned.m8n8.x4.trans.shared.b16 {%0,%1,%2,%3}, [%4];"
        : "=r"(r[0]), "=r"(r[1]), "=r"(r[2]), "=r"(r[3]) : "r"(a));
}
__device__ __forceinline__ void mma16816(float* c, const uint32_t* a, const uint32_t* b) {
    asm volatile("mma.sync.aligned.m16n8k16.row.col.f32.bf16.bf16.f32 "
        "{%0,%1,%2,%3}, {%4,%5,%6,%7}, {%8,%9}, {%0,%1,%2,%3};"
        : "+f"(c[0]), "+f"(c[1]), "+f"(c[2]), "+f"(c[3])
        : "r"(a[0]), "r"(a[1]), "r"(a[2]), "r"(a[3]), "r"(b[0]), "r"(b[1]));
}
__device__ __forceinline__ void bf16_split2(float x, float y,
                                            __nv_bfloat162& hi, __nv_bfloat162& lo) {
    hi = __floats2bfloat162_rn(x, y);
    lo = __floats2bfloat162_rn(x - __bfloat162float(hi.x), y - __bfloat162float(hi.y));
}

// ---------------------------------------------------------------------------
// Bucket nodes by type + tile-base prefix
// ---------------------------------------------------------------------------
__global__ void k_zero() { if (threadIdx.x < Tt) g_cnt[threadIdx.x] = 0; }

__global__ void __launch_bounds__(256) k_bucket(const int* __restrict__ type_id) {
    __shared__ int scnt[Tt];
    __shared__ int sbase[Tt];
    const int tid = threadIdx.x;
    if (tid < Tt) scnt[tid] = 0;
    __syncthreads();
    const int n = blockIdx.x * 256 + tid;
    const int t = type_id[n];
    const int local = atomicAdd(&scnt[t], 1);
    __syncthreads();
    if (tid < Tt) sbase[tid] = atomicAdd(&g_cnt[tid], scnt[tid]);
    __syncthreads();
    g_perm[t][sbase[t] + local] = n;
}

__global__ void k_prefix() {
    if (threadIdx.x == 0) {
        int f = 0, i = 0;
        g_baseF[0] = 0; g_baseI[0] = 0;
        for (int t = 0; t < Tt; t++) {
            f += (g_cnt[t] + 7) >> 3;
            i += (g_cnt[t] + 63) >> 6;
            g_baseF[t + 1] = f;
            g_baseI[t + 1] = i;
        }
    }
}

// ---------------------------------------------------------------------------
// Weight prep: bf16 hi/lo split of U_f and U_iou (row-major [i][j])
// ---------------------------------------------------------------------------
__global__ void __launch_bounds__(256) k_prepw(const float* __restrict__ U_iou,
                                               const float* __restrict__ U_f) {
    int idx = blockIdx.x * 256 + threadIdx.x;     // 4 * 4 * 16384 = 262144
    int t   = idx >> 16;
    int rem = idx & 65535;
    int m   = rem >> 14;                          // 0 = f, 1..3 = iou jtile
    int i   = (rem >> 7) & 127;
    int j   = rem & 127;
    float v = (m == 0) ? U_f[((size_t)t * Hs + i) * Hs + j]
                       : U_iou[((size_t)t * Hs + i) * 3 * Hs + (m - 1) * Hs + j];
    __nv_bfloat16 hi = __float2bfloat16(v);
    __nv_bfloat16 lo = __float2bfloat16(v - __bfloat162float(hi));
    int e = i * Hs + j;
    if (m == 0) { g_Bf[0][t][e] = hi; g_Bf[1][t][e] = lo; }
    else        { g_Bi[0][t][m - 1][e] = hi; g_Bi[1][t][m - 1][e] = lo; }
}

// ---------------------------------------------------------------------------
// k_fmma: 8 nodes/CTA, rows = nl*8+k (M=64), K=128, N=128.
// D = h_tile @ U_f[t] via 3-pass bf16-split mma.sync; fused h_sum + sigmoid*c
// epilogue with smem-staged k-reduction. 2 CTAs/SM (regs<=128, smem ~104.5KB).
// smem: A_hi[64][136] | A_lo | B_hi[128][136] | B_lo | s_node
// stage (fp32 64x136) aliases A_hi+A_lo after MMA completes.
// ---------------------------------------------------------------------------
__global__ void __launch_bounds__(256, 2) k_fmma(
    const float* __restrict__ h, const float* __restrict__ c_in,
    const float* __restrict__ f_input, const float* __restrict__ b_f,
    float* __restrict__ out)
{
    // bid -> (type, tile)
    int bid = blockIdx.x;
    if (bid >= g_baseF[Tt]) return;
    int t = 0;
    #pragma unroll
    for (int tt = 1; tt < Tt; tt++) t += (bid >= g_baseF[tt]);
    const int tile = bid - g_baseF[t];
    const int cnt  = g_cnt[t];

    extern __shared__ __align__(16) char sm[];
    __nv_bfloat16* Ah = (__nv_bfloat16*)sm;                 // 64*136*2 = 17408
    __nv_bfloat16* Al = Ah + 64 * APAD;
    __nv_bfloat16* Bh = Al + 64 * APAD;                     // 128*136*2 = 34816
    __nv_bfloat16* Bl = Bh + Hs * APAD;
    float*         stage = (float*)sm;                      // 64*136*4 aliases Ah+Al
    int*           s_node = (int*)(sm + (2 * 64 + 2 * Hs) * APAD * 2);
    const uint32_t su = smem_to_u32(sm);
    const uint32_t aHi = su, aLo = su + 17408, bHi = su + 34816, bLo = su + 69632;

    const int tid  = threadIdx.x;
    const int wid  = tid >> 5, lane = tid & 31;

    if (tid < 8) s_node[tid] = g_perm[t][min(tile * 8 + tid, cnt - 1)];
    __syncthreads();

    // ---- A gather: split h to bf16 hi/lo, fuse h_sum -> global ----
    {
        const int cp  = (tid & 63) * 2;
        const int grp = tid >> 6;             // 4 groups x 2 nodes
        #pragma unroll
        for (int nn = 0; nn < 2; nn++) {
            const int nl = grp * 2 + nn;
            const size_t nb = (size_t)s_node[nl] * (Kc * Hs);
            float hx = 0.f, hy = 0.f;
            #pragma unroll
            for (int k = 0; k < Kc; k++) {
                float2 v = *(const float2*)(h + nb + k * Hs + cp);
                hx += v.x; hy += v.y;
                __nv_bfloat162 hi2, lo2;
                bf16_split2(v.x, v.y, hi2, lo2);
                const int row = nl * 8 + k;
                *(__nv_bfloat162*)(Ah + row * APAD + cp) = hi2;
                *(__nv_bfloat162*)(Al + row * APAD + cp) = lo2;
            }
            *(float2*)(g_hsum + (size_t)s_node[nl] * Hs + cp) = make_float2(hx, hy);
        }
    }
    // ---- B copy (pre-split, L2-hot), add padding ----
    {
        const uint4* sh = (const uint4*)g_Bf[0][t];
        const uint4* sl = (const uint4*)g_Bf[1][t];
        #pragma unroll
        for (int i = tid; i < 2048; i += 256) {
            int row = i >> 4, q = i & 15;
            *(uint4*)(Bh + row * APAD + q * 8) = sh[i];
            *(uint4*)(Bl + row * APAD + q * 8) = sl[i];
        }
    }
    __syncthreads();

    // ---- 3-pass MMA: warp grid 2(M) x 4(N), acc 32/thread ----
    const int wm = wid & 1, wn = wid >> 1;
    const int l15 = lane & 15, lh = (lane >> 4) << 3;
    float acc[2][4][4];
    #pragma unroll
    for (int mt = 0; mt < 2; mt++)
        #pragma unroll
        for (int nt = 0; nt < 4; nt++)
            #pragma unroll
            for (int e = 0; e < 4; e++) acc[mt][nt][e] = 0.f;

    #pragma unroll
    for (int pass = 0; pass < 3; pass++) {
        const uint32_t Ab = (pass == 2) ? aLo : aHi;
        const uint32_t Bb = (pass == 1) ? bLo : bHi;
        #pragma unroll
        for (int ks = 0; ks < 8; ks++) {
            uint32_t a[2][4];
            #pragma unroll
            for (int mt = 0; mt < 2; mt++)
                ldm_x4(a[mt], Ab + (((wm * 32 + mt * 16 + l15) * APAD + ks * 16 + lh) << 1));
            uint32_t b[4][2];
            #pragma unroll
            for (int nb = 0; nb < 2; nb++) {
                uint32_t r[4];
                ldm_x4t(r, Bb + (((ks * 16 + l15) * APAD + wn * 32 + nb * 16 + lh) << 1));
                b[nb * 2][0] = r[0]; b[nb * 2][1] = r[1];
                b[nb * 2 + 1][0] = r[2]; b[nb * 2 + 1][1] = r[3];
            }
            #pragma unroll
            for (int mt = 0; mt < 2; mt++)
                #pragma unroll
                for (int nt = 0; nt < 4; nt++)
                    mma16816(acc[mt][nt], a[mt], b[nt]);
        }
    }
    __syncthreads();   // all warps done reading A before stage overwrites it

    // ---- Epilogue: sigmoid(D + f_input + b_f) * c -> stage ----
    {
        const int q  = lane & 3;           // col quad
        const int lr = lane >> 2;          // row-in-8
        float2 bfv[4];
        #pragma unroll
        for (int nt = 0; nt < 4; nt++)
            bfv[nt] = *(const float2*)(b_f + t * Hs + wn * 32 + nt * 8 + q * 2);
        #pragma unroll
        for (int mt = 0; mt < 2; mt++) {
            #pragma unroll
            for (int half = 0; half < 2; half++) {
                const int row = wm * 32 + mt * 16 + lr + half * 8;
                const int nl = row >> 3, kk = row & 7;
                const size_t node = (size_t)s_node[nl];
                const float* fi = f_input + node * Hs;
                const float* cr = c_in + node * (Kc * Hs) + kk * Hs;
                #pragma unroll
                for (int nt = 0; nt < 4; nt++) {
                    const int col = wn * 32 + nt * 8 + q * 2;
                    float2 f2 = *(const float2*)(fi + col);
                    float2 c2 = *(const float2*)(cr + col);
                    float x0 = acc[mt][nt][half * 2 + 0] + f2.x + bfv[nt].x;
                    float x1 = acc[mt][nt][half * 2 + 1] + f2.y + bfv[nt].y;
                    float g0 = 1.f / (1.f + __expf(-x0));
                    float g1 = 1.f / (1.f + __expf(-x1));
                    *(float2*)(stage + row * APAD + col) = make_float2(g0 * c2.x, g1 * c2.y);
                }
            }
        }
    }
    __syncthreads();

    // ---- k-reduction + coalesced c_aggr store ----
    #pragma unroll
    for (int x = tid; x < 8 * Hs; x += 256) {
        const int nl = x >> 7, j = x & 127;
        if (tile * 8 + nl < cnt) {
            float s = 0.f;
            #pragma unroll
            for (int k = 0; k < Kc; k++) s += stage[(nl * 8 + k) * APAD + j];
            out[(size_t)s_node[nl] * (4 * Hs) + 3 * Hs + j] = s;
        }
    }
}

// ---------------------------------------------------------------------------
// k_imma: 64 nodes/CTA (M=64 rows = h_sum), K=128, 3 j-tiles of N=128.
// Direct register epilogue, sector-aligned float2 stores. 2 CTAs/SM.
// ---------------------------------------------------------------------------
__global__ void __launch_bounds__(256, 2) k_imma(
    const float* __restrict__ b_iou, float* __restrict__ out)
{
    int bid = blockIdx.x;
    if (bid >= g_baseI[Tt]) return;
    int t = 0;
    #pragma unroll
    for (int tt = 1; tt < Tt; tt++) t += (bid >= g_baseI[tt]);
    const int tile = bid - g_baseI[t];
    const int cnt  = g_cnt[t];

    extern __shared__ __align__(16) char sm[];
    __nv_bfloat16* Ah = (__nv_bfloat16*)sm;
    __nv_bfloat16* Al = Ah + 64 * APAD;
    __nv_bfloat16* Bh = Al + 64 * APAD;
    __nv_bfloat16* Bl = Bh + Hs * APAD;
    int*           s_node = (int*)(sm + (2 * 64 + 2 * Hs) * APAD * 2);
    const uint32_t su = smem_to_u32(sm);
    const uint32_t aHi = su, aLo = su + 17408, bHi = su + 34816, bLo = su + 69632;

    const int tid = threadIdx.x;
    const int wid = tid >> 5, lane = tid & 31;

    if (tid < 64) s_node[tid] = g_perm[t][min(tile * 64 + tid, cnt - 1)];
    __syncthreads();

    // ---- A gather: split h_sum rows ----
    {
        const int cp  = (tid & 63) * 2;
        const int grp = tid >> 6;
        #pragma unroll 4
        for (int rr = 0; rr < 16; rr++) {
            const int row = grp * 16 + rr;
            float2 v = *(const float2*)(g_hsum + (size_t)s_node[row] * Hs + cp);
            __nv_bfloat162 hi2, lo2;
            bf16_split2(v.x, v.y, hi2, lo2);
            *(__nv_bfloat162*)(Ah + row * APAD + cp) = hi2;
            *(__nv_bfloat162*)(Al + row * APAD + cp) = lo2;
        }
    }

    const int wm = wid & 1, wn = wid >> 1;
    const int l15 = lane & 15, lh = (lane >> 4) << 3;
    const int q = lane & 3, lr = lane >> 2;

    for (int jt = 0; jt < 3; jt++) {
        __syncthreads();   // prior MMA reads done before B overwrite; A visible on jt=0
        {
            const uint4* sh = (const uint4*)g_Bi[0][t][jt];
            const uint4* sl = (const uint4*)g_Bi[1][t][jt];
            #pragma unroll
            for (int i = tid; i < 2048; i += 256) {
                int row = i >> 4, qq = i & 15;
                *(uint4*)(Bh + row * APAD + qq * 8) = sh[i];
                *(uint4*)(Bl + row * APAD + qq * 8) = sl[i];
            }
        }
        __syncthreads();

        float acc[2][4][4];
        #pragma unroll
        for (int mt = 0; mt < 2; mt++)
            #pragma unroll
            for (int nt = 0; nt < 4; nt++)
                #pragma unroll
                for (int e = 0; e < 4; e++) acc[mt][nt][e] = 0.f;

        #pragma unroll
        for (int pass = 0; pass < 3; pass++) {
            const uint32_t Ab = (pass == 2) ? aLo : aHi;
            const uint32_t Bb = (pass == 1) ? bLo : bHi;
            #pragma unroll
            for (int ks = 0; ks < 8; ks++) {
                uint32_t a[2][4];
                #pragma unroll
                for (int mt = 0; mt < 2; mt++)
                    ldm_x4(a[mt], Ab + (((wm * 32 + mt * 16 + l15) * APAD + ks * 16 + lh) << 1));
                uint32_t b[4][2];
                #pragma unroll
                for (int nb = 0; nb < 2; nb++) {
                    uint32_t r[4];
                    ldm_x4t(r, Bb + (((ks * 16 + l15) * APAD + wn * 32 + nb * 16 + lh) << 1));
                    b[nb * 2][0] = r[0]; b[nb * 2][1] = r[1];
                    b[nb * 2 + 1][0] = r[2]; b[nb * 2 + 1][1] = r[3];
                }
                #pragma unroll
                for (int mt = 0; mt < 2; mt++)
                    #pragma unroll
                    for (int nt = 0; nt < 4; nt++)
                        mma16816(acc[mt][nt], a[mt], b[nt]);
            }
        }

        // ---- Direct epilogue: + b_iou, store ----
        float2 bv[4];
        #pragma unroll
        for (int nt = 0; nt < 4; nt++)
            bv[nt] = *(const float2*)(b_iou + (size_t)t * 3 * Hs + jt * Hs + wn * 32 + nt * 8 + q * 2);
        #pragma unroll
        for (int mt = 0; mt < 2; mt++) {
            #pragma unroll
            for (int half = 0; half < 2; half++) {
                const int row = wm * 32 + mt * 16 + lr + half * 8;
                if (tile * 64 + row < cnt) {
                    float* orow = out + (size_t)s_node[row] * (4 * Hs) + jt * Hs;
                    #pragma unroll
                    for (int nt = 0; nt < 4; nt++) {
                        const int col = wn * 32 + nt * 8 + q * 2;
                        *(float2*)(orow + col) = make_float2(
                            acc[mt][nt][half * 2 + 0] + bv[nt].x,
                            acc[mt][nt][half * 2 + 1] + bv[nt].y);
                    }
                }
            }
        }
    }
}

// ---------------------------------------------------------------------------
extern "C" void kernel_launch(void* const* d_in, const int* in_sizes, int n_in,
                              void* d_out, int out_size)
{
    const float* h       = (const float*)d_in[0];
    const float* c       = (const float*)d_in[1];
    const float* f_input = (const float*)d_in[2];
    const int*   type_id = (const int*)  d_in[3];
    const float* U_iou   = (const float*)d_in[4];
    const float* b_iou   = (const float*)d_in[5];
    const float* U_f     = (const float*)d_in[6];
    const float* b_f     = (const float*)d_in[7];
    float*       out     = (float*)d_out;

    const int smemF = (2 * 64 + 2 * Hs) * APAD * 2 + 8 * 4;     // 104480
    const int smemI = (2 * 64 + 2 * Hs) * APAD * 2 + 64 * 4;    // 104704
    cudaFuncSetAttribute(k_fmma, cudaFuncAttributeMaxDynamicSharedMemorySize, smemF);
    cudaFuncSetAttribute(k_imma, cudaFuncAttributeMaxDynamicSharedMemorySize, smemI);

    k_zero<<<1, 32>>>();
    k_bucket<<<Nn / 256, 256>>>(type_id);
    k_prefix<<<1, 32>>>();
    k_prepw<<<1024, 256>>>(U_iou, U_f);

    k_fmma<<<Nn / 8 + Tt, 256, smemF>>>(h, c, f_input, b_f, out);
    k_imma<<<Nn / 64 + Tt, 256, smemI>>>(b_iou, out);
}

// round 7
// speedup vs baseline: 2.9602x; 1.1379x over previous
#include <cuda_runtime.h>
#include <cuda_bf16.h>
#include <cuda_fp16.h>
#include <cstdint>
#include <math.h>

#define Nn 65536
#define Kc 8
#define Hs 128
#define Tt 4
#define APAD 136          // padded row stride in 16-bit elems (272B: conflict-free ldmatrix)

// ---------------------------------------------------------------------------
// Device scratch (allocation-free rule: __device__ globals)
// ---------------------------------------------------------------------------
__device__ int   g_cnt[Tt];
__device__ int   g_perm[Tt][Nn];
__device__ int   g_baseF[Tt + 1];   // tile bases, 8 nodes/tile
__device__ int   g_baseI[Tt + 1];   // tile bases, 64 nodes/tile
__device__ float g_hsum[(size_t)Nn * Hs];
__device__ __align__(16) __half        g_Bf[Tt][Hs * Hs];        // fp16 U_f
__device__ __align__(16) __nv_bfloat16 g_Bi[2][Tt][3][Hs * Hs];  // bf16 hi/lo U_iou

// ---------------------------------------------------------------------------
// Warp-MMA helpers (sm_80-class: valid on plain sm_103 target)
// ---------------------------------------------------------------------------
__device__ __forceinline__ uint32_t smem_to_u32(const void* p) {
    uint32_t a;
    asm("{ .reg .u64 t; cvta.to.shared.u64 t, %1; cvt.u32.u64 %0, t; }" : "=r"(a) : "l"(p));
    return a;
}
__device__ __forceinline__ void ldm_x4(uint32_t* r, uint32_t a) {
    asm volatile("ldmatrix.sync.aligned.m8n8.x4.shared.b16 {%0,%1,%2,%3}, [%4];"
        : "=r"(r[0]), "=r"(r[1]), "=r"(r[2]), "=r"(r[3]) : "r"(a));
}
__device__ __forceinline__ void ldm_x4t(uint32_t* r, uint32_t a) {
    asm volatile("ldmatrix.sync.aligned.m8n8.x4.trans.shared.b16 {%0,%1,%2,%3}, [%4];"
        : "=r"(r[0]), "=r"(r[1]), "=r"(r[2]), "=r"(r[3]) : "r"(a));
}
__device__ __forceinline__ void mma16816bf(float* c, const uint32_t* a, const uint32_t* b) {
    asm volatile("mma.sync.aligned.m16n8k16.row.col.f32.bf16.bf16.f32 "
        "{%0,%1,%2,%3}, {%4,%5,%6,%7}, {%8,%9}, {%0,%1,%2,%3};"
        : "+f"(c[0]), "+f"(c[1]), "+f"(c[2]), "+f"(c[3])
        : "r"(a[0]), "r"(a[1]), "r"(a[2]), "r"(a[3]), "r"(b[0]), "r"(b[1]));
}
__device__ __forceinline__ void mma16816h(float* c, const uint32_t* a, const uint32_t* b) {
    asm volatile("mma.sync.aligned.m16n8k16.row.col.f32.f16.f16.f32 "
        "{%0,%1,%2,%3}, {%4,%5,%6,%7}, {%8,%9}, {%0,%1,%2,%3};"
        : "+f"(c[0]), "+f"(c[1]), "+f"(c[2]), "+f"(c[3])
        : "r"(a[0]), "r"(a[1]), "r"(a[2]), "r"(a[3]), "r"(b[0]), "r"(b[1]));
}
__device__ __forceinline__ void bf16_split2(float x, float y,
                                            __nv_bfloat162& hi, __nv_bfloat162& lo) {
    hi = __floats2bfloat162_rn(x, y);
    lo = __floats2bfloat162_rn(x - __bfloat162float(hi.x), y - __bfloat162float(hi.y));
}

// ---------------------------------------------------------------------------
// Bucket nodes by type + tile-base prefix
// ---------------------------------------------------------------------------
__global__ void k_zero() { if (threadIdx.x < Tt) g_cnt[threadIdx.x] = 0; }

__global__ void __launch_bounds__(256) k_bucket(const int* __restrict__ type_id) {
    __shared__ int scnt[Tt];
    __shared__ int sbase[Tt];
    const int tid = threadIdx.x;
    if (tid < Tt) scnt[tid] = 0;
    __syncthreads();
    const int n = blockIdx.x * 256 + tid;
    const int t = type_id[n];
    const int local = atomicAdd(&scnt[t], 1);
    __syncthreads();
    if (tid < Tt) sbase[tid] = atomicAdd(&g_cnt[tid], scnt[tid]);
    __syncthreads();
    g_perm[t][sbase[t] + local] = n;
}

__global__ void k_prefix() {
    if (threadIdx.x == 0) {
        int f = 0, i = 0;
        g_baseF[0] = 0; g_baseI[0] = 0;
        for (int t = 0; t < Tt; t++) {
            f += (g_cnt[t] + 7) >> 3;
            i += (g_cnt[t] + 63) >> 6;
            g_baseF[t + 1] = f;
            g_baseI[t + 1] = i;
        }
    }
}

// ---------------------------------------------------------------------------
// Weight prep: fp16 U_f; bf16 hi/lo U_iou (row-major [i][j])
// ---------------------------------------------------------------------------
__global__ void __launch_bounds__(256) k_prepw(const float* __restrict__ U_iou,
                                               const float* __restrict__ U_f) {
    int idx = blockIdx.x * 256 + threadIdx.x;     // 4 * 4 * 16384 = 262144
    int t   = idx >> 16;
    int rem = idx & 65535;
    int m   = rem >> 14;                          // 0 = f, 1..3 = iou jtile
    int i   = (rem >> 7) & 127;
    int j   = rem & 127;
    int e   = i * Hs + j;
    if (m == 0) {
        g_Bf[t][e] = __float2half(U_f[((size_t)t * Hs + i) * Hs + j]);
    } else {
        float v = U_iou[((size_t)t * Hs + i) * 3 * Hs + (m - 1) * Hs + j];
        __nv_bfloat16 hi = __float2bfloat16(v);
        __nv_bfloat16 lo = __float2bfloat16(v - __bfloat162float(hi));
        g_Bi[0][t][m - 1][e] = hi; g_Bi[1][t][m - 1][e] = lo;
    }
}

// ---------------------------------------------------------------------------
// k_fmma: 8 nodes/CTA, rows = nl*8+k (M=64), K=128, N=128.
// Single-pass fp16 mma.sync (sigmoid contracts the quantization error);
// fused h_sum + sigmoid*c epilogue with smem-staged k-reduction.
// 3 CTAs/SM (smem ~52KB, regs<=85).
// smem: A[64][136] fp16 | B[128][136] fp16 | s_node; stage fp32 aliases A|B.
// ---------------------------------------------------------------------------
__global__ void __launch_bounds__(256, 3) k_fmma(
    const float* __restrict__ h, const float* __restrict__ c_in,
    const float* __restrict__ f_input, const float* __restrict__ b_f,
    float* __restrict__ out)
{
    int bid = blockIdx.x;
    if (bid >= g_baseF[Tt]) return;
    int t = 0;
    #pragma unroll
    for (int tt = 1; tt < Tt; tt++) t += (bid >= g_baseF[tt]);
    const int tile = bid - g_baseF[t];
    const int cnt  = g_cnt[t];

    extern __shared__ __align__(16) char sm[];
    __half* Af = (__half*)sm;                       // 64*136*2  = 17408
    __half* Bf = Af + 64 * APAD;                    // 128*136*2 = 34816
    float*  stage = (float*)sm;                     // 64*136*4 = 34816 aliases A|B
    int*    s_node = (int*)(sm + 52224);
    const uint32_t su = smem_to_u32(sm);
    const uint32_t aOff = su, bOff = su + 17408;

    const int tid  = threadIdx.x;
    const int wid  = tid >> 5, lane = tid & 31;

    if (tid < 8) s_node[tid] = g_perm[t][min(tile * 8 + tid, cnt - 1)];
    __syncthreads();

    // ---- A gather: h -> fp16, fuse h_sum -> global ----
    {
        const int cp  = (tid & 63) * 2;
        const int grp = tid >> 6;             // 4 groups x 2 nodes
        #pragma unroll
        for (int nn = 0; nn < 2; nn++) {
            const int nl = grp * 2 + nn;
            const size_t nb = (size_t)s_node[nl] * (Kc * Hs);
            float hx = 0.f, hy = 0.f;
            #pragma unroll
            for (int k = 0; k < Kc; k++) {
                float2 v = *(const float2*)(h + nb + k * Hs + cp);
                hx += v.x; hy += v.y;
                *(__half2*)(Af + (nl * 8 + k) * APAD + cp) = __floats2half2_rn(v.x, v.y);
            }
            *(float2*)(g_hsum + (size_t)s_node[nl] * Hs + cp) = make_float2(hx, hy);
        }
    }
    // ---- B copy (fp16, L2-hot), add padding ----
    {
        const uint4* sh = (const uint4*)g_Bf[t];
        #pragma unroll
        for (int i = tid; i < 2048; i += 256) {
            int row = i >> 4, q = i & 15;
            *(uint4*)(Bf + row * APAD + q * 8) = sh[i];
        }
    }
    __syncthreads();

    // ---- Single-pass fp16 MMA: warp grid 2(M) x 4(N), acc 32/thread ----
    const int wm = wid & 1, wn = wid >> 1;
    const int l15 = lane & 15, lh = (lane >> 4) << 3;
    float acc[2][4][4];
    #pragma unroll
    for (int mt = 0; mt < 2; mt++)
        #pragma unroll
        for (int nt = 0; nt < 4; nt++)
            #pragma unroll
            for (int e = 0; e < 4; e++) acc[mt][nt][e] = 0.f;

    #pragma unroll
    for (int ks = 0; ks < 8; ks++) {
        uint32_t a[2][4];
        #pragma unroll
        for (int mt = 0; mt < 2; mt++)
            ldm_x4(a[mt], aOff + (((wm * 32 + mt * 16 + l15) * APAD + ks * 16 + lh) << 1));
        uint32_t b[4][2];
        #pragma unroll
        for (int nb = 0; nb < 2; nb++) {
            uint32_t r[4];
            ldm_x4t(r, bOff + (((ks * 16 + l15) * APAD + wn * 32 + nb * 16 + lh) << 1));
            b[nb * 2][0] = r[0]; b[nb * 2][1] = r[1];
            b[nb * 2 + 1][0] = r[2]; b[nb * 2 + 1][1] = r[3];
        }
        #pragma unroll
        for (int mt = 0; mt < 2; mt++)
            #pragma unroll
            for (int nt = 0; nt < 4; nt++)
                mma16816h(acc[mt][nt], a[mt], b[nt]);
    }
    __syncthreads();   // all warps done reading A/B before stage overwrites them

    // ---- Epilogue: sigmoid(D + f_input + b_f) * c -> stage ----
    {
        const int q  = lane & 3;           // col quad
        const int lr = lane >> 2;          // row-in-8
        float2 bfv[4];
        #pragma unroll
        for (int nt = 0; nt < 4; nt++)
            bfv[nt] = *(const float2*)(b_f + t * Hs + wn * 32 + nt * 8 + q * 2);
        #pragma unroll
        for (int mt = 0; mt < 2; mt++) {
            #pragma unroll
            for (int half = 0; half < 2; half++) {
                const int row = wm * 32 + mt * 16 + lr + half * 8;
                const int nl = row >> 3, kk = row & 7;
                const size_t node = (size_t)s_node[nl];
                const float* fi = f_input + node * Hs;
                const float* cr = c_in + node * (Kc * Hs) + kk * Hs;
                #pragma unroll
                for (int nt = 0; nt < 4; nt++) {
                    const int col = wn * 32 + nt * 8 + q * 2;
                    float2 f2 = *(const float2*)(fi + col);
                    float2 c2 = *(const float2*)(cr + col);
                    float x0 = acc[mt][nt][half * 2 + 0] + f2.x + bfv[nt].x;
                    float x1 = acc[mt][nt][half * 2 + 1] + f2.y + bfv[nt].y;
                    float g0 = 1.f / (1.f + __expf(-x0));
                    float g1 = 1.f / (1.f + __expf(-x1));
                    *(float2*)(stage + row * APAD + col) = make_float2(g0 * c2.x, g1 * c2.y);
                }
            }
        }
    }
    __syncthreads();

    // ---- k-reduction + coalesced c_aggr store ----
    #pragma unroll
    for (int x = tid; x < 8 * Hs; x += 256) {
        const int nl = x >> 7, j = x & 127;
        if (tile * 8 + nl < cnt) {
            float s = 0.f;
            #pragma unroll
            for (int k = 0; k < Kc; k++) s += stage[(nl * 8 + k) * APAD + j];
            out[(size_t)s_node[nl] * (4 * Hs) + 3 * Hs + j] = s;
        }
    }
}

// ---------------------------------------------------------------------------
// k_imma: 64 nodes/CTA (M=64 rows = h_sum), K=128, 3 j-tiles of N=128.
// 3-pass bf16-split (raw linear output needs the accuracy). 2 CTAs/SM.
// ---------------------------------------------------------------------------
__global__ void __launch_bounds__(256, 2) k_imma(
    const float* __restrict__ b_iou, float* __restrict__ out)
{
    int bid = blockIdx.x;
    if (bid >= g_baseI[Tt]) return;
    int t = 0;
    #pragma unroll
    for (int tt = 1; tt < Tt; tt++) t += (bid >= g_baseI[tt]);
    const int tile = bid - g_baseI[t];
    const int cnt  = g_cnt[t];

    extern __shared__ __align__(16) char sm[];
    __nv_bfloat16* Ah = (__nv_bfloat16*)sm;
    __nv_bfloat16* Al = Ah + 64 * APAD;
    __nv_bfloat16* Bh = Al + 64 * APAD;
    __nv_bfloat16* Bl = Bh + Hs * APAD;
    int*           s_node = (int*)(sm + (2 * 64 + 2 * Hs) * APAD * 2);
    const uint32_t su = smem_to_u32(sm);
    const uint32_t aHi = su, aLo = su + 17408, bHi = su + 34816, bLo = su + 69632;

    const int tid = threadIdx.x;
    const int wid = tid >> 5, lane = tid & 31;

    if (tid < 64) s_node[tid] = g_perm[t][min(tile * 64 + tid, cnt - 1)];
    __syncthreads();

    // ---- A gather: split h_sum rows ----
    {
        const int cp  = (tid & 63) * 2;
        const int grp = tid >> 6;
        #pragma unroll 4
        for (int rr = 0; rr < 16; rr++) {
            const int row = grp * 16 + rr;
            float2 v = *(const float2*)(g_hsum + (size_t)s_node[row] * Hs + cp);
            __nv_bfloat162 hi2, lo2;
            bf16_split2(v.x, v.y, hi2, lo2);
            *(__nv_bfloat162*)(Ah + row * APAD + cp) = hi2;
            *(__nv_bfloat162*)(Al + row * APAD + cp) = lo2;
        }
    }

    const int wm = wid & 1, wn = wid >> 1;
    const int l15 = lane & 15, lh = (lane >> 4) << 3;
    const int q = lane & 3, lr = lane >> 2;

    for (int jt = 0; jt < 3; jt++) {
        __syncthreads();   // prior MMA reads done before B overwrite; A visible on jt=0
        {
            const uint4* sh = (const uint4*)g_Bi[0][t][jt];
            const uint4* sl = (const uint4*)g_Bi[1][t][jt];
            #pragma unroll
            for (int i = tid; i < 2048; i += 256) {
                int row = i >> 4, qq = i & 15;
                *(uint4*)(Bh + row * APAD + qq * 8) = sh[i];
                *(uint4*)(Bl + row * APAD + qq * 8) = sl[i];
            }
        }
        __syncthreads();

        float acc[2][4][4];
        #pragma unroll
        for (int mt = 0; mt < 2; mt++)
            #pragma unroll
            for (int nt = 0; nt < 4; nt++)
                #pragma unroll
                for (int e = 0; e < 4; e++) acc[mt][nt][e] = 0.f;

        #pragma unroll
        for (int pass = 0; pass < 3; pass++) {
            const uint32_t Ab = (pass == 2) ? aLo : aHi;
            const uint32_t Bb = (pass == 1) ? bLo : bHi;
            #pragma unroll
            for (int ks = 0; ks < 8; ks++) {
                uint32_t a[2][4];
                #pragma unroll
                for (int mt = 0; mt < 2; mt++)
                    ldm_x4(a[mt], Ab + (((wm * 32 + mt * 16 + l15) * APAD + ks * 16 + lh) << 1));
                uint32_t b[4][2];
                #pragma unroll
                for (int nb = 0; nb < 2; nb++) {
                    uint32_t r[4];
                    ldm_x4t(r, Bb + (((ks * 16 + l15) * APAD + wn * 32 + nb * 16 + lh) << 1));
                    b[nb * 2][0] = r[0]; b[nb * 2][1] = r[1];
                    b[nb * 2 + 1][0] = r[2]; b[nb * 2 + 1][1] = r[3];
                }
                #pragma unroll
                for (int mt = 0; mt < 2; mt++)
                    #pragma unroll
                    for (int nt = 0; nt < 4; nt++)
                        mma16816bf(acc[mt][nt], a[mt], b[nt]);
            }
        }

        // ---- Direct epilogue: + b_iou, store ----
        float2 bv[4];
        #pragma unroll
        for (int nt = 0; nt < 4; nt++)
            bv[nt] = *(const float2*)(b_iou + (size_t)t * 3 * Hs + jt * Hs + wn * 32 + nt * 8 + q * 2);
        #pragma unroll
        for (int mt = 0; mt < 2; mt++) {
            #pragma unroll
            for (int half = 0; half < 2; half++) {
                const int row = wm * 32 + mt * 16 + lr + half * 8;
                if (tile * 64 + row < cnt) {
                    float* orow = out + (size_t)s_node[row] * (4 * Hs) + jt * Hs;
                    #pragma unroll
                    for (int nt = 0; nt < 4; nt++) {
                        const int col = wn * 32 + nt * 8 + q * 2;
                        *(float2*)(orow + col) = make_float2(
                            acc[mt][nt][half * 2 + 0] + bv[nt].x,
                            acc[mt][nt][half * 2 + 1] + bv[nt].y);
                    }
                }
            }
        }
    }
}

// ---------------------------------------------------------------------------
extern "C" void kernel_launch(void* const* d_in, const int* in_sizes, int n_in,
                              void* d_out, int out_size)
{
    const float* h       = (const float*)d_in[0];
    const float* c       = (const float*)d_in[1];
    const float* f_input = (const float*)d_in[2];
    const int*   type_id = (const int*)  d_in[3];
    const float* U_iou   = (const float*)d_in[4];
    const float* b_iou   = (const float*)d_in[5];
    const float* U_f     = (const float*)d_in[6];
    const float* b_f     = (const float*)d_in[7];
    float*       out     = (float*)d_out;

    const int smemF = 52224 + 8 * 4;                            // 52256
    const int smemI = (2 * 64 + 2 * Hs) * APAD * 2 + 64 * 4;    // 104704
    cudaFuncSetAttribute(k_fmma, cudaFuncAttributeMaxDynamicSharedMemorySize, smemF);
    cudaFuncSetAttribute(k_imma, cudaFuncAttributeMaxDynamicSharedMemorySize, smemI);

    k_zero<<<1, 32>>>();
    k_bucket<<<Nn / 256, 256>>>(type_id);
    k_prefix<<<1, 32>>>();
    k_prepw<<<1024, 256>>>(U_iou, U_f);

    k_fmma<<<Nn / 8 + Tt, 256, smemF>>>(h, c, f_input, b_f, out);
    k_imma<<<Nn / 64 + Tt, 256, smemI>>>(b_iou, out);
}

// round 8
// speedup vs baseline: 4.3561x; 1.4716x over previous
#include <cuda_runtime.h>
#include <cuda_bf16.h>
#include <cuda_fp16.h>
#include <cstdint>
#include <math.h>

#define Nn 65536
#define Kc 8
#define Hs 128
#define Tt 4
#define APAD 136          // padded row stride in 16-bit elems (272B: conflict-free ldmatrix)

// ---------------------------------------------------------------------------
// Device scratch (allocation-free rule: __device__ globals)
// ---------------------------------------------------------------------------
__device__ int   g_cnt[Tt];
__device__ int   g_perm[Tt][Nn];
__device__ float g_hsum[(size_t)Nn * Hs];
__device__ __align__(16) __half        g_Bf[Tt][Hs * Hs];        // fp16 U_f
__device__ __align__(16) __nv_bfloat16 g_Bi[2][Tt][3][Hs * Hs];  // bf16 hi/lo U_iou

// ---------------------------------------------------------------------------
// Warp-MMA helpers (sm_80-class: valid on plain sm_103 target)
// ---------------------------------------------------------------------------
__device__ __forceinline__ uint32_t smem_to_u32(const void* p) {
    uint32_t a;
    asm("{ .reg .u64 t; cvta.to.shared.u64 t, %1; cvt.u32.u64 %0, t; }" : "=r"(a) : "l"(p));
    return a;
}
__device__ __forceinline__ void ldm_x4(uint32_t* r, uint32_t a) {
    asm volatile("ldmatrix.sync.aligned.m8n8.x4.shared.b16 {%0,%1,%2,%3}, [%4];"
        : "=r"(r[0]), "=r"(r[1]), "=r"(r[2]), "=r"(r[3]) : "r"(a));
}
__device__ __forceinline__ void ldm_x4t(uint32_t* r, uint32_t a) {
    asm volatile("ldmatrix.sync.aligned.m8n8.x4.trans.shared.b16 {%0,%1,%2,%3}, [%4];"
        : "=r"(r[0]), "=r"(r[1]), "=r"(r[2]), "=r"(r[3]) : "r"(a));
}
__device__ __forceinline__ void mma16816bf(float* c, const uint32_t* a, const uint32_t* b) {
    asm volatile("mma.sync.aligned.m16n8k16.row.col.f32.bf16.bf16.f32 "
        "{%0,%1,%2,%3}, {%4,%5,%6,%7}, {%8,%9}, {%0,%1,%2,%3};"
        : "+f"(c[0]), "+f"(c[1]), "+f"(c[2]), "+f"(c[3])
        : "r"(a[0]), "r"(a[1]), "r"(a[2]), "r"(a[3]), "r"(b[0]), "r"(b[1]));
}
__device__ __forceinline__ void mma16816h(float* c, const uint32_t* a, const uint32_t* b) {
    asm volatile("mma.sync.aligned.m16n8k16.row.col.f32.f16.f16.f32 "
        "{%0,%1,%2,%3}, {%4,%5,%6,%7}, {%8,%9}, {%0,%1,%2,%3};"
        : "+f"(c[0]), "+f"(c[1]), "+f"(c[2]), "+f"(c[3])
        : "r"(a[0]), "r"(a[1]), "r"(a[2]), "r"(a[3]), "r"(b[0]), "r"(b[1]));
}
__device__ __forceinline__ void bf16_split2(float x, float y,
                                            __nv_bfloat162& hi, __nv_bfloat162& lo) {
    hi = __floats2bfloat162_rn(x, y);
    lo = __floats2bfloat162_rn(x - __bfloat162float(hi.x), y - __bfloat162float(hi.y));
}

// ---------------------------------------------------------------------------
// Bucket nodes by type
// ---------------------------------------------------------------------------
__global__ void k_zero() { if (threadIdx.x < Tt) g_cnt[threadIdx.x] = 0; }

__global__ void __launch_bounds__(256) k_bucket(const int* __restrict__ type_id) {
    __shared__ int scnt[Tt];
    __shared__ int sbase[Tt];
    const int tid = threadIdx.x;
    if (tid < Tt) scnt[tid] = 0;
    __syncthreads();
    const int n = blockIdx.x * 256 + tid;
    const int t = type_id[n];
    const int local = atomicAdd(&scnt[t], 1);
    __syncthreads();
    if (tid < Tt) sbase[tid] = atomicAdd(&g_cnt[tid], scnt[tid]);
    __syncthreads();
    g_perm[t][sbase[t] + local] = n;
}

// ---------------------------------------------------------------------------
// Weight prep: fp16 U_f; bf16 hi/lo U_iou (row-major [i][j])
// ---------------------------------------------------------------------------
__global__ void __launch_bounds__(256) k_prepw(const float* __restrict__ U_iou,
                                               const float* __restrict__ U_f) {
    int idx = blockIdx.x * 256 + threadIdx.x;     // 262144
    int t   = idx >> 16;
    int rem = idx & 65535;
    int m   = rem >> 14;                          // 0 = f, 1..3 = iou jtile
    int i   = (rem >> 7) & 127;
    int j   = rem & 127;
    int e   = i * Hs + j;
    if (m == 0) {
        g_Bf[t][e] = __float2half(U_f[((size_t)t * Hs + i) * Hs + j]);
    } else {
        float v = U_iou[((size_t)t * Hs + i) * 3 * Hs + (m - 1) * Hs + j];
        __nv_bfloat16 hi = __float2bfloat16(v);
        __nv_bfloat16 lo = __float2bfloat16(v - __bfloat162float(hi));
        g_Bi[0][t][m - 1][e] = hi; g_Bi[1][t][m - 1][e] = lo;
    }
}

// ---------------------------------------------------------------------------
// k_fmma: PERSISTENT. grid = 4 types x 111 slots. B_f[t] fp16 resident in
// smem; CTA strides over 8-node tiles (M=64, K=128, N=128, single-pass fp16).
// One __syncthreads per tile (A double-buffered); epilogue does
// sigmoid(D+f_input+b_f)*c and reduces over the 8 children via shfl.bfly.
// smem: B[128][136] fp16 (34816) | A0[64][136] | A1[64][136] (17408 each)
// ---------------------------------------------------------------------------
#define FSLOTS 111
__global__ void __launch_bounds__(256, 3) k_fmma(
    const float* __restrict__ h, const float* __restrict__ c_in,
    const float* __restrict__ f_input, const float* __restrict__ b_f,
    float* __restrict__ out)
{
    const int t    = blockIdx.x & 3;
    const int slot = blockIdx.x >> 2;
    const int cnt  = g_cnt[t];
    const int ntiles = (cnt + 7) >> 3;

    extern __shared__ __align__(16) char sm[];
    __half* Bf = (__half*)sm;                       // 34816
    __half* A0 = (__half*)(sm + 34816);
    const uint32_t su = smem_to_u32(sm);
    const uint32_t bOff = su;

    const int tid  = threadIdx.x;
    const int wid  = tid >> 5, lane = tid & 31;
    const int wm = wid & 1, wn = wid >> 1;
    const int l15 = lane & 15, lh = (lane >> 4) << 3;
    const int q = lane & 3, lr = lane >> 2;
    const int* perm = g_perm[t];

    // ---- B load once (L2-hot), padded ----
    {
        const uint4* sh = (const uint4*)g_Bf[t];
        #pragma unroll
        for (int i = tid; i < 2048; i += 256) {
            int row = i >> 4, qq = i & 15;
            *(uint4*)(Bf + row * APAD + qq * 8) = sh[i];
        }
    }
    // bias preload (constant per CTA)
    float2 bfv[4];
    #pragma unroll
    for (int nt = 0; nt < 4; nt++)
        bfv[nt] = *(const float2*)(b_f + t * Hs + wn * 32 + nt * 8 + q * 2);

    const int cp  = (tid & 63) * 2;
    const int grp = tid >> 6;

    int buf = 0;
    for (int tile = slot; tile < ntiles; tile += FSLOTS, buf ^= 1) {
        __half* Af = A0 + buf * (64 * APAD);
        const uint32_t aOff = su + 34816 + buf * 17408;

        // ---- gather: h -> fp16 smem, fused h_sum -> global ----
        #pragma unroll
        for (int nn = 0; nn < 2; nn++) {
            const int nl = grp * 2 + nn;
            const int n  = perm[min(tile * 8 + nl, cnt - 1)];
            const size_t nb = (size_t)n * (Kc * Hs);
            float hx = 0.f, hy = 0.f;
            #pragma unroll
            for (int k = 0; k < Kc; k++) {
                float2 v = *(const float2*)(h + nb + k * Hs + cp);
                hx += v.x; hy += v.y;
                *(__half2*)(Af + (nl * 8 + k) * APAD + cp) = __floats2half2_rn(v.x, v.y);
            }
            *(float2*)(g_hsum + (size_t)n * Hs + cp) = make_float2(hx, hy);
        }
        __syncthreads();   // gather visible (covers B on first tile)

        // ---- single-pass fp16 MMA ----
        float acc[2][4][4];
        #pragma unroll
        for (int mt = 0; mt < 2; mt++)
            #pragma unroll
            for (int nt = 0; nt < 4; nt++)
                #pragma unroll
                for (int e = 0; e < 4; e++) acc[mt][nt][e] = 0.f;

        #pragma unroll
        for (int ks = 0; ks < 8; ks++) {
            uint32_t a[2][4];
            #pragma unroll
            for (int mt = 0; mt < 2; mt++)
                ldm_x4(a[mt], aOff + (((wm * 32 + mt * 16 + l15) * APAD + ks * 16 + lh) << 1));
            uint32_t b[4][2];
            #pragma unroll
            for (int nb2 = 0; nb2 < 2; nb2++) {
                uint32_t r[4];
                ldm_x4t(r, bOff + (((ks * 16 + l15) * APAD + wn * 32 + nb2 * 16 + lh) << 1));
                b[nb2 * 2][0] = r[0]; b[nb2 * 2][1] = r[1];
                b[nb2 * 2 + 1][0] = r[2]; b[nb2 * 2 + 1][1] = r[3];
            }
            #pragma unroll
            for (int mt = 0; mt < 2; mt++)
                #pragma unroll
                for (int nt = 0; nt < 4; nt++)
                    mma16816h(acc[mt][nt], a[mt], b[nt]);
        }

        // ---- epilogue: sigmoid(D + f_input + b_f) * c, shfl k-reduction ----
        #pragma unroll
        for (int mt = 0; mt < 2; mt++) {
            const int na_l = wm * 4 + mt * 2;          // local nodes na_l, na_l+1
            const int na = perm[min(tile * 8 + na_l, cnt - 1)];
            const int nb = perm[min(tile * 8 + na_l + 1, cnt - 1)];
            const float* fa = f_input + (size_t)na * Hs;
            const float* fb = f_input + (size_t)nb * Hs;
            const float* ca = c_in + (size_t)na * (Kc * Hs) + lr * Hs;
            const float* cb = c_in + (size_t)nb * (Kc * Hs) + lr * Hs;
            #pragma unroll
            for (int nt = 0; nt < 4; nt++) {
                const int col = wn * 32 + nt * 8 + q * 2;
                float2 f2a = *(const float2*)(fa + col);
                float2 f2b = *(const float2*)(fb + col);
                float2 c2a = *(const float2*)(ca + col);
                float2 c2b = *(const float2*)(cb + col);
                float x0 = acc[mt][nt][0] + f2a.x + bfv[nt].x;
                float x1 = acc[mt][nt][1] + f2a.y + bfv[nt].y;
                float x2 = acc[mt][nt][2] + f2b.x + bfv[nt].x;
                float x3 = acc[mt][nt][3] + f2b.y + bfv[nt].y;
                float v0 = c2a.x / (1.f + __expf(-x0));
                float v1 = c2a.y / (1.f + __expf(-x1));
                float v2 = c2b.x / (1.f + __expf(-x2));
                float v3 = c2b.y / (1.f + __expf(-x3));
                #pragma unroll
                for (int d = 4; d < 32; d <<= 1) {
                    v0 += __shfl_xor_sync(0xFFFFFFFFu, v0, d);
                    v1 += __shfl_xor_sync(0xFFFFFFFFu, v1, d);
                    v2 += __shfl_xor_sync(0xFFFFFFFFu, v2, d);
                    v3 += __shfl_xor_sync(0xFFFFFFFFu, v3, d);
                }
                if (lr == 0) {
                    if (tile * 8 + na_l < cnt)
                        *(float2*)(out + (size_t)na * (4 * Hs) + 3 * Hs + col) = make_float2(v0, v1);
                    if (tile * 8 + na_l + 1 < cnt)
                        *(float2*)(out + (size_t)nb * (4 * Hs) + 3 * Hs + col) = make_float2(v2, v3);
                }
            }
        }
        // one sync per tile is enough: next gather writes buf^1, which no
        // in-flight reader uses (readers of buf^1 finished before this
        // iteration's __syncthreads).
    }
}

// ---------------------------------------------------------------------------
// k_imma: PERSISTENT per (type, jtile). grid = 12 groups x 25 slots.
// B_iou[t][jt] hi/lo resident in smem; CTA strides over 64-node tiles
// (M=64, K=128, N=128, 3-pass bf16-split). Direct register epilogue.
// smem: Ah|Al (34816) | Bh|Bl (69632)
// ---------------------------------------------------------------------------
#define ISLOTS 25
__global__ void __launch_bounds__(256, 2) k_imma(
    const float* __restrict__ b_iou, float* __restrict__ out)
{
    const int grpid = blockIdx.x % 12;
    const int slot  = blockIdx.x / 12;
    const int t  = grpid & 3;
    const int jt = grpid >> 2;          // 0..2
    const int cnt = g_cnt[t];
    const int ntiles = (cnt + 63) >> 6;

    extern __shared__ __align__(16) char sm[];
    __nv_bfloat16* Ah = (__nv_bfloat16*)sm;
    __nv_bfloat16* Al = Ah + 64 * APAD;
    __nv_bfloat16* Bh = Al + 64 * APAD;
    __nv_bfloat16* Bl = Bh + Hs * APAD;
    const uint32_t su = smem_to_u32(sm);
    const uint32_t aHi = su, aLo = su + 17408, bHi = su + 34816, bLo = su + 69632;

    const int tid = threadIdx.x;
    const int wid = tid >> 5, lane = tid & 31;
    const int wm = wid & 1, wn = wid >> 1;
    const int l15 = lane & 15, lh = (lane >> 4) << 3;
    const int q = lane & 3, lr = lane >> 2;
    const int* perm = g_perm[t];

    // ---- B load once ----
    {
        const uint4* sh = (const uint4*)g_Bi[0][t][jt];
        const uint4* sl = (const uint4*)g_Bi[1][t][jt];
        #pragma unroll
        for (int i = tid; i < 2048; i += 256) {
            int row = i >> 4, qq = i & 15;
            *(uint4*)(Bh + row * APAD + qq * 8) = sh[i];
            *(uint4*)(Bl + row * APAD + qq * 8) = sl[i];
        }
    }
    float2 bv[4];
    #pragma unroll
    for (int nt = 0; nt < 4; nt++)
        bv[nt] = *(const float2*)(b_iou + (size_t)t * 3 * Hs + jt * Hs + wn * 32 + nt * 8 + q * 2);

    const int cp  = (tid & 63) * 2;
    const int grp = tid >> 6;

    for (int tile = slot; tile < ntiles; tile += ISLOTS) {
        // ---- A gather: split h_sum rows ----
        #pragma unroll 4
        for (int rr = 0; rr < 16; rr++) {
            const int row = grp * 16 + rr;
            const int n = perm[min(tile * 64 + row, cnt - 1)];
            float2 v = *(const float2*)(g_hsum + (size_t)n * Hs + cp);
            __nv_bfloat162 hi2, lo2;
            bf16_split2(v.x, v.y, hi2, lo2);
            *(__nv_bfloat162*)(Ah + row * APAD + cp) = hi2;
            *(__nv_bfloat162*)(Al + row * APAD + cp) = lo2;
        }
        __syncthreads();   // A visible (covers B on first tile)

        float acc[2][4][4];
        #pragma unroll
        for (int mt = 0; mt < 2; mt++)
            #pragma unroll
            for (int nt = 0; nt < 4; nt++)
                #pragma unroll
                for (int e = 0; e < 4; e++) acc[mt][nt][e] = 0.f;

        #pragma unroll
        for (int pass = 0; pass < 3; pass++) {
            const uint32_t Ab = (pass == 2) ? aLo : aHi;
            const uint32_t Bb = (pass == 1) ? bLo : bHi;
            #pragma unroll
            for (int ks = 0; ks < 8; ks++) {
                uint32_t a[2][4];
                #pragma unroll
                for (int mt = 0; mt < 2; mt++)
                    ldm_x4(a[mt], Ab + (((wm * 32 + mt * 16 + l15) * APAD + ks * 16 + lh) << 1));
                uint32_t b[4][2];
                #pragma unroll
                for (int nb2 = 0; nb2 < 2; nb2++) {
                    uint32_t r[4];
                    ldm_x4t(r, Bb + (((ks * 16 + l15) * APAD + wn * 32 + nb2 * 16 + lh) << 1));
                    b[nb2 * 2][0] = r[0]; b[nb2 * 2][1] = r[1];
                    b[nb2 * 2 + 1][0] = r[2]; b[nb2 * 2 + 1][1] = r[3];
                }
                #pragma unroll
                for (int mt = 0; mt < 2; mt++)
                    #pragma unroll
                    for (int nt = 0; nt < 4; nt++)
                        mma16816bf(acc[mt][nt], a[mt], b[nt]);
            }
        }

        // ---- direct epilogue: + b_iou, store ----
        #pragma unroll
        for (int mt = 0; mt < 2; mt++) {
            #pragma unroll
            for (int half = 0; half < 2; half++) {
                const int row = wm * 32 + mt * 16 + lr + half * 8;
                if (tile * 64 + row < cnt) {
                    float* orow = out + (size_t)perm[tile * 64 + row] * (4 * Hs) + jt * Hs;
                    #pragma unroll
                    for (int nt = 0; nt < 4; nt++) {
                        const int col = wn * 32 + nt * 8 + q * 2;
                        *(float2*)(orow + col) = make_float2(
                            acc[mt][nt][half * 2 + 0] + bv[nt].x,
                            acc[mt][nt][half * 2 + 1] + bv[nt].y);
                    }
                }
            }
        }
        __syncthreads();   // MMA/epilogue done before next gather overwrites A
    }
}

// ---------------------------------------------------------------------------
extern "C" void kernel_launch(void* const* d_in, const int* in_sizes, int n_in,
                              void* d_out, int out_size)
{
    const float* h       = (const float*)d_in[0];
    const float* c       = (const float*)d_in[1];
    const float* f_input = (const float*)d_in[2];
    const int*   type_id = (const int*)  d_in[3];
    const float* U_iou   = (const float*)d_in[4];
    const float* b_iou   = (const float*)d_in[5];
    const float* U_f     = (const float*)d_in[6];
    const float* b_f     = (const float*)d_in[7];
    float*       out     = (float*)d_out;

    const int smemF = 34816 + 2 * 17408;    // 69632
    const int smemI = 34816 + 69632;        // 104448
    cudaFuncSetAttribute(k_fmma, cudaFuncAttributeMaxDynamicSharedMemorySize, smemF);
    cudaFuncSetAttribute(k_imma, cudaFuncAttributeMaxDynamicSharedMemorySize, smemI);

    k_zero<<<1, 32>>>();
    k_bucket<<<Nn / 256, 256>>>(type_id);
    k_prepw<<<1024, 256>>>(U_iou, U_f);

    k_fmma<<<4 * FSLOTS, 256, smemF>>>(h, c, f_input, b_f, out);
    k_imma<<<12 * ISLOTS, 256, smemI>>>(b_iou, out);
}